// round 14
// baseline (speedup 1.0000x reference)
#include <cuda_runtime.h>
#include <cuda_bf16.h>

#define N_NODES 100000
#define N_EDGES 1600000
#define IN_DIM  256
#define HIDDEN  64

#define DOT_BLOCKS  12500          // 8 warps/block -> warp per node (R11 best)
#define EDGE_PAIRS  (N_EDGES / 2)  // 800000 int2 loads
#define SCAT_BLOCKS (EDGE_PAIRS / 256)              // 3125
#define OUT_BLOCKS  ((N_NODES + 255) / 256)         // 391

// Scratch (__device__ globals; zero at module load; fused kernel re-zeros)
__device__ __align__(16) float g_u[IN_DIM];    // W @ w2
__device__ float g_c;                           // b.w2 + b2
__device__ __align__(16) float2 g_sd[N_NODES];  // .x = raw s[v], .y = edge count
__device__ __align__(16) float  g_t[N_NODES];   // aggregated normalized ss[src]
__device__ unsigned g_done;                     // scatter-block completion counter
__device__ unsigned g_done2;                    // out-block completion counter

// K1: single block computes u = W@w2 (256 threads) and c = b.w2 + b2
__global__ void __launch_bounds__(256) k_prep(
        const float* __restrict__ W, const float* __restrict__ b,
        const float* __restrict__ w2, const float* __restrict__ b2) {
    __shared__ __align__(16) float s_w2[HIDDEN];
    int i = threadIdx.x;               // 256 == IN_DIM
    if (i < HIDDEN) s_w2[i] = w2[i];
    __syncthreads();
    const float4* wr = (const float4*)(W + (size_t)i * HIDDEN);
    float acc = 0.f;
#pragma unroll
    for (int q = 0; q < HIDDEN / 4; q++) {
        float4 wv = wr[q];
        acc += wv.x * s_w2[q*4+0] + wv.y * s_w2[q*4+1]
             + wv.z * s_w2[q*4+2] + wv.w * s_w2[q*4+3];
    }
    g_u[i] = acc;
    if (i == 0) {
        float cc = b2[0];
        for (int h = 0; h < HIDDEN; h++) cc += b[h] * s_w2[h];
        g_c = cc;
    }
}

// K2 (PDL secondary of prep): prefetch x + deg atomics before the dependency
// sync (neither needs g_u); then sync and finish the dot. Warp per node.
__global__ void __launch_bounds__(256) k_dotdeg(
        const float* __restrict__ x, const int* __restrict__ dst) {
    const int tid  = threadIdx.x;
    const int gtid = blockIdx.x * 256 + tid;
    const int node = gtid >> 5;        // 0..99999 exactly
    const int lane = tid & 31;

    const float4* xp = (const float4*)(x + (size_t)node * IN_DIM);
    float4 a0 = __ldcs(&xp[lane]);
    float4 a1 = __ldcs(&xp[lane + 32]);

    if (gtid < EDGE_PAIRS) {
        int2 p = ((const int2*)dst)[gtid];
        if ((unsigned)p.x < (unsigned)N_NODES) atomicAdd(&g_sd[p.x].y, 1.0f);
        if ((unsigned)p.y < (unsigned)N_NODES) atomicAdd(&g_sd[p.y].y, 1.0f);
    }

#if __CUDA_ARCH__ >= 900
    cudaGridDependencySynchronize();   // wait for k_prep's g_u
#endif

    const float4* up = (const float4*)g_u;
    float4 u0 = up[lane];
    float4 u1 = up[lane + 32];
    float acc = a0.x*u0.x + a0.y*u0.y + a0.z*u0.z + a0.w*u0.w
              + a1.x*u1.x + a1.y*u1.y + a1.z*u1.z + a1.w*u1.w;
#pragma unroll
    for (int o = 16; o; o >>= 1) acc += __shfl_xor_sync(0xffffffffu, acc, o);
    if (lane == 0) g_sd[node].x = acc;   // RAW
}

// K3 (PDL secondary of dotdeg): fused scatter + out.
//   Blocks [0, SCAT_BLOCKS): prefetch indices pre-sync, gather+RED, then
//     fence + bump g_done.
//   Blocks [SCAT_BLOCKS, +OUT_BLOCKS): spin until g_done==SCAT_BLOCKS
//     (scheduled last in bid order -> short spin, no deadlock), then sigmoid
//     out + reset state for graph replay.
__global__ void __launch_bounds__(256) k_scatout(const int* __restrict__ src,
                                                 const int* __restrict__ dst,
                                                 float* __restrict__ out) {
    const int tid = threadIdx.x;
    if (blockIdx.x < SCAT_BLOCKS) {
        int i = blockIdx.x * 256 + tid;
        int2 s = ((const int2*)src)[i];
        int2 d = ((const int2*)dst)[i];
#if __CUDA_ARCH__ >= 900
        cudaGridDependencySynchronize();   // wait for k_dotdeg's g_sd
#endif
        float v0 = 0.f, v1 = 0.f;
        if ((unsigned)s.x < (unsigned)N_NODES) {
            float2 sd = g_sd[s.x];
            v0 = sd.x * rsqrtf(1.0f + sd.y);
        }
        if ((unsigned)s.y < (unsigned)N_NODES) {
            float2 sd = g_sd[s.y];
            v1 = sd.x * rsqrtf(1.0f + sd.y);
        }
        if ((unsigned)d.x < (unsigned)N_NODES) atomicAdd(&g_t[d.x], v0);
        if ((unsigned)d.y < (unsigned)N_NODES) atomicAdd(&g_t[d.y], v1);
        __threadfence();
        __syncthreads();
        if (tid == 0) atomicAdd(&g_done, 1u);
    } else {
#if __CUDA_ARCH__ >= 900
        cudaGridDependencySynchronize();
#endif
        if (tid == 0) {
            while (atomicAdd(&g_done, 0u) < (unsigned)SCAT_BLOCKS)
                __nanosleep(64);
        }
        __syncthreads();
        __threadfence();                   // acquire g_t
        int v = (blockIdx.x - SCAT_BLOCKS) * 256 + tid;
        if (v < N_NODES) {
            float2 sd = g_sd[v];
            float  t  = g_t[v];
            float di = rsqrtf(1.0f + sd.y);
            float z  = di * (t + sd.x * di) + g_c;
            out[v] = 1.0f / (1.0f + expf(-z));
            g_sd[v] = make_float2(sd.x, 0.f);
            g_t[v]  = 0.f;
        }
        __syncthreads();
        if (tid == 0) {
            unsigned n = atomicAdd(&g_done2, 1u) + 1u;
            if (n == (unsigned)OUT_BLOCKS) {   // last out block resets counters
                g_done  = 0u;
                g_done2 = 0u;
                __threadfence();
            }
        }
    }
}

static void launch_pdl(const void* fn, dim3 grid, dim3 block, void** args) {
    cudaLaunchConfig_t cfg = {};
    cfg.gridDim = grid;
    cfg.blockDim = block;
    cfg.dynamicSmemBytes = 0;
    cfg.stream = (cudaStream_t)0;
    cudaLaunchAttribute attr[1];
    attr[0].id = cudaLaunchAttributeProgrammaticStreamSerialization;
    attr[0].val.programmaticStreamSerializationAllowed = 1;
    cfg.attrs = attr;
    cfg.numAttrs = 1;
    cudaLaunchKernelExC(&cfg, fn, args);
}

extern "C" void kernel_launch(void* const* d_in, const int* in_sizes, int n_in,
                              void* d_out, int out_size) {
    const float* x   = (const float*)d_in[0];
    const int*   ei  = (const int*)d_in[1];   // [2, N_EDGES], materialized as int32
    const float* W   = (const float*)d_in[2];
    const float* b   = (const float*)d_in[3];
    const float* w2  = (const float*)d_in[4];
    const float* b2  = (const float*)d_in[5];
    float*       out = (float*)d_out;

    const int* src = ei;
    const int* dst = ei + N_EDGES;

    k_prep<<<1, 256>>>(W, b, w2, b2);

    {
        void* args[] = {(void*)&x, (void*)&dst};
        launch_pdl((const void*)k_dotdeg, dim3(DOT_BLOCKS), dim3(256), args);
    }
    {
        void* args[] = {(void*)&src, (void*)&dst, (void*)&out};
        launch_pdl((const void*)k_scatout,
                   dim3(SCAT_BLOCKS + OUT_BLOCKS), dim3(256), args);
    }
}

// round 15
// speedup vs baseline: 1.2099x; 1.2099x over previous
#include <cuda_runtime.h>
#include <cuda_bf16.h>

#define N_NODES 100000
#define N_EDGES 1600000
#define IN_DIM  256
#define HIDDEN  64

#define DOT_BLOCKS 12500          // 8 warps/block -> warp per node
#define EDGE_PAIRS (N_EDGES / 2)  // 800000 int2 loads
#define PREP_BLOCKS 33            // 32 blocks u (warp/output), block 32 -> c

// Scratch (__device__ globals; zero at module load; k_out re-zeros for replay)
__device__ __align__(16) float g_u[IN_DIM];    // W @ w2
__device__ float g_c;                           // b.w2 + b2
__device__ __align__(16) float2 g_sd[N_NODES];  // .x = raw s[v], .y = edge count
__device__ __align__(16) float  g_t[N_NODES];   // aggregated normalized ss[src]

// K1: warp per output element. Block i (<32), warp w -> u[i*8+w].
//     Lane l handles W[row*64 + l] and W[row*64 + 32 + l].
//     Block 32, warp 0 computes c = b.w2 + b2 by warp reduction.
__global__ void __launch_bounds__(256) k_prep(
        const float* __restrict__ W, const float* __restrict__ b,
        const float* __restrict__ w2, const float* __restrict__ b2) {
    const int wid  = threadIdx.x >> 5;
    const int lane = threadIdx.x & 31;
    float wa = w2[lane];
    float wb = w2[lane + 32];
    if (blockIdx.x < 32) {
        int row = blockIdx.x * 8 + wid;          // 0..255
        const float* wr = W + (size_t)row * HIDDEN;
        float acc = wr[lane] * wa + wr[lane + 32] * wb;
#pragma unroll
        for (int o = 16; o; o >>= 1) acc += __shfl_xor_sync(0xffffffffu, acc, o);
        if (lane == 0) g_u[row] = acc;
    } else if (wid == 0) {
        float acc = b[lane] * wa + b[lane + 32] * wb;
#pragma unroll
        for (int o = 16; o; o >>= 1) acc += __shfl_xor_sync(0xffffffffu, acc, o);
        if (lane == 0) g_c = acc + b2[0];
    }
}

// K2 (PDL secondary of prep): prefetch x + deg atomics before the dependency
// sync (neither needs g_u); then sync and finish the dot. Warp per node.
__global__ void __launch_bounds__(256) k_dotdeg(
        const float* __restrict__ x, const int* __restrict__ dst) {
    const int tid  = threadIdx.x;
    const int gtid = blockIdx.x * 256 + tid;
    const int node = gtid >> 5;        // 0..99999 exactly
    const int lane = tid & 31;

    // independent prefetch: x row (evict-first -> protect L2 for tables+indices)
    const float4* xp = (const float4*)(x + (size_t)node * IN_DIM);
    float4 a0 = __ldcs(&xp[lane]);
    float4 a1 = __ldcs(&xp[lane + 32]);

    // stowaway degree work (default policy: dst row lingers in L2 for scatter)
    if (gtid < EDGE_PAIRS) {
        int2 p = ((const int2*)dst)[gtid];
        if ((unsigned)p.x < (unsigned)N_NODES) atomicAdd(&g_sd[p.x].y, 1.0f);
        if ((unsigned)p.y < (unsigned)N_NODES) atomicAdd(&g_sd[p.y].y, 1.0f);
    }

#if __CUDA_ARCH__ >= 900
    cudaGridDependencySynchronize();   // wait for k_prep's g_u
#endif

    const float4* up = (const float4*)g_u;
    float4 u0 = up[lane];
    float4 u1 = up[lane + 32];
    float acc = a0.x*u0.x + a0.y*u0.y + a0.z*u0.z + a0.w*u0.w
              + a1.x*u1.x + a1.y*u1.y + a1.z*u1.z + a1.w*u1.w;
#pragma unroll
    for (int o = 16; o; o >>= 1) acc += __shfl_xor_sync(0xffffffffu, acc, o);
    if (lane == 0) g_sd[node].x = acc;   // RAW
}

// K3 (PDL secondary of dotdeg): prefetch src/dst indices, sync, gather + RED.
__global__ void __launch_bounds__(256) k_scatter(const int* __restrict__ src,
                                                 const int* __restrict__ dst) {
    int i = blockIdx.x * 256 + threadIdx.x;
    int2 s = make_int2(-1, -1), d = make_int2(-1, -1);
    if (i < EDGE_PAIRS) {
        s = ((const int2*)src)[i];
        d = ((const int2*)dst)[i];
    }
#if __CUDA_ARCH__ >= 900
    cudaGridDependencySynchronize();   // wait for k_dotdeg's g_sd
#endif
    if (i < EDGE_PAIRS) {
        float v0 = 0.f, v1 = 0.f;
        if ((unsigned)s.x < (unsigned)N_NODES) {
            float2 sd = g_sd[s.x];
            v0 = sd.x * rsqrtf(1.0f + sd.y);
        }
        if ((unsigned)s.y < (unsigned)N_NODES) {
            float2 sd = g_sd[s.y];
            v1 = sd.x * rsqrtf(1.0f + sd.y);
        }
        if ((unsigned)d.x < (unsigned)N_NODES) atomicAdd(&g_t[d.x], v0);
        if ((unsigned)d.y < (unsigned)N_NODES) atomicAdd(&g_t[d.y], v1);
    }
}

// K4 (PDL secondary of scatter, sync-at-top): 1 node/thread.
__global__ void __launch_bounds__(256) k_out(float* __restrict__ out) {
#if __CUDA_ARCH__ >= 900
    cudaGridDependencySynchronize();
#endif
    int v = blockIdx.x * 256 + threadIdx.x;
    if (v < N_NODES) {
        float2 sd = g_sd[v];
        float  t  = g_t[v];
        float di = rsqrtf(1.0f + sd.y);
        float z  = di * (t + sd.x * di) + g_c;
        out[v] = 1.0f / (1.0f + expf(-z));
        g_sd[v] = make_float2(sd.x, 0.f);   // reset degree
        g_t[v]  = 0.f;
    }
}

static void launch_pdl(const void* fn, dim3 grid, dim3 block, void** args) {
    cudaLaunchConfig_t cfg = {};
    cfg.gridDim = grid;
    cfg.blockDim = block;
    cfg.dynamicSmemBytes = 0;
    cfg.stream = (cudaStream_t)0;
    cudaLaunchAttribute attr[1];
    attr[0].id = cudaLaunchAttributeProgrammaticStreamSerialization;
    attr[0].val.programmaticStreamSerializationAllowed = 1;
    cfg.attrs = attr;
    cfg.numAttrs = 1;
    cudaLaunchKernelExC(&cfg, fn, args);
}

extern "C" void kernel_launch(void* const* d_in, const int* in_sizes, int n_in,
                              void* d_out, int out_size) {
    const float* x   = (const float*)d_in[0];
    const int*   ei  = (const int*)d_in[1];   // [2, N_EDGES], materialized as int32
    const float* W   = (const float*)d_in[2];
    const float* b   = (const float*)d_in[3];
    const float* w2  = (const float*)d_in[4];
    const float* b2  = (const float*)d_in[5];
    float*       out = (float*)d_out;

    const int* src = ei;
    const int* dst = ei + N_EDGES;

    k_prep<<<PREP_BLOCKS, 256>>>(W, b, w2, b2);

    {
        void* args[] = {(void*)&x, (void*)&dst};
        launch_pdl((const void*)k_dotdeg, dim3(DOT_BLOCKS), dim3(256), args);
    }
    {
        void* args[] = {(void*)&src, (void*)&dst};
        launch_pdl((const void*)k_scatter,
                   dim3((EDGE_PAIRS + 255) / 256), dim3(256), args);
    }
    {
        void* args[] = {(void*)&out};
        launch_pdl((const void*)k_out,
                   dim3((N_NODES + 255) / 256), dim3(256), args);
    }
}